// round 1
// baseline (speedup 1.0000x reference)
#include <cuda_runtime.h>

// Problem constants (from reference: B, S, D = 16, 4096, 512)
#define BB 16
#define SS 4096
#define DD 512

// Scratch (no allocations allowed) — per-batch compacted source indices + counts
__device__ int g_src[BB * SS];
__device__ int g_counts[BB];

// ---------------------------------------------------------------------------
// Kernel 1: per-batch stable compaction index build.
// One block per batch. 1024 threads x 4 elements = 4096. Block exclusive scan
// of keep flags gives each kept element its packed rank (stable: original
// order preserved, matching jnp.argsort's stable sort on the 0/1 key).
// ---------------------------------------------------------------------------
__global__ void __launch_bounds__(1024)
scan_kernel(const float* __restrict__ probs, const float* __restrict__ uniform) {
    const int b = blockIdx.x;
    const int t = threadIdx.x;
    const int PER = SS / 1024;  // 4
    const int base = b * SS + t * PER;

    int keep[PER];
    int local = 0;
#pragma unroll
    for (int i = 0; i < PER; i++) {
        keep[i] = (uniform[base + i] >= probs[base + i]) ? 1 : 0;
        local += keep[i];
    }

    // Block-wide inclusive scan of per-thread sums (warp shuffle + smem).
    const int lane = t & 31;
    const int warp = t >> 5;
    int v = local;
#pragma unroll
    for (int o = 1; o < 32; o <<= 1) {
        int u = __shfl_up_sync(0xffffffffu, v, o);
        if (lane >= o) v += u;
    }
    __shared__ int warp_sums[32];
    if (lane == 31) warp_sums[warp] = v;
    __syncthreads();
    if (warp == 0) {
        int w = warp_sums[lane];
#pragma unroll
        for (int o = 1; o < 32; o <<= 1) {
            int u = __shfl_up_sync(0xffffffffu, w, o);
            if (lane >= o) w += u;
        }
        warp_sums[lane] = w;
    }
    __syncthreads();

    int excl = v - local + (warp > 0 ? warp_sums[warp - 1] : 0);

    int r = excl;
#pragma unroll
    for (int i = 0; i < PER; i++) {
        if (keep[i]) {
            g_src[b * SS + r] = t * PER + i;
            r++;
        }
    }
    if (t == 1023) g_counts[b] = excl + local;  // total kept this batch
}

// ---------------------------------------------------------------------------
// Kernel 2: gather + pad. One 128-thread block per output row (b, j).
// Row = 512 fp32 = 128 float4 -> one float4 per thread (coalesced read of a
// contiguous 2KB source row, coalesced write). j >= count_b -> zeros.
// Thread 0 also writes the mask element.
// ---------------------------------------------------------------------------
__global__ void __launch_bounds__(128)
gather_kernel(const float* __restrict__ x,
              float* __restrict__ out_padded,
              float* __restrict__ out_mask,
              int max_length) {
    const int j = blockIdx.x;
    const int b = blockIdx.y;
    const int count = g_counts[b];

    float4* dst = reinterpret_cast<float4*>(
        out_padded + (long long)(b * max_length + j) * DD);

    if (j < count) {
        const int s = g_src[b * SS + j];
        const float4* src = reinterpret_cast<const float4*>(
            x + ((long long)b * SS + s) * DD);
        dst[threadIdx.x] = src[threadIdx.x];
    } else {
        dst[threadIdx.x] = make_float4(0.f, 0.f, 0.f, 0.f);
    }

    if (threadIdx.x == 0) {
        out_mask[b * max_length + j] = (j < count) ? 1.0f : 0.0f;
    }
}

// ---------------------------------------------------------------------------
// Launch: out_size = B*ML*D + B*ML  =>  ML = out_size / (B*(D+1))
// Output layout: padded (B*ML*D floats) followed by masks (B*ML floats).
// ---------------------------------------------------------------------------
extern "C" void kernel_launch(void* const* d_in, const int* in_sizes, int n_in,
                              void* d_out, int out_size) {
    const float* x       = (const float*)d_in[0];
    const float* probs   = (const float*)d_in[1];
    const float* uniform = (const float*)d_in[2];
    float* out = (float*)d_out;

    const int max_length = out_size / (BB * (DD + 1));
    float* out_mask = out + (long long)BB * max_length * DD;

    scan_kernel<<<BB, 1024>>>(probs, uniform);

    dim3 grid(max_length, BB);
    gather_kernel<<<grid, 128>>>(x, out, out_mask, max_length);
}

// round 2
// speedup vs baseline: 1.2323x; 1.2323x over previous
#include <cuda_runtime.h>

// Problem constants (from reference: B, S, D = 16, 4096, 512)
#define BB 16
#define SS 4096
#define DD 512

// Scratch — per-batch compacted source indices + counts
__device__ int g_src[BB * SS];
__device__ int g_counts[BB];

// ---------------------------------------------------------------------------
// Kernel 1: per-batch stable compaction index build.
// One block per batch. 1024 threads x 4 elements. Block exclusive scan of
// keep flags gives each kept element its packed rank (stable order).
// ---------------------------------------------------------------------------
__global__ void __launch_bounds__(1024)
scan_kernel(const float* __restrict__ probs, const float* __restrict__ uniform) {
    const int b = blockIdx.x;
    const int t = threadIdx.x;
    const int PER = SS / 1024;  // 4
    const int base = b * SS + t * PER;

    int keep[PER];
    int local = 0;
#pragma unroll
    for (int i = 0; i < PER; i++) {
        keep[i] = (uniform[base + i] >= probs[base + i]) ? 1 : 0;
        local += keep[i];
    }

    const int lane = t & 31;
    const int warp = t >> 5;
    int v = local;
#pragma unroll
    for (int o = 1; o < 32; o <<= 1) {
        int u = __shfl_up_sync(0xffffffffu, v, o);
        if (lane >= o) v += u;
    }
    __shared__ int warp_sums[32];
    if (lane == 31) warp_sums[warp] = v;
    __syncthreads();
    if (warp == 0) {
        int w = warp_sums[lane];
#pragma unroll
        for (int o = 1; o < 32; o <<= 1) {
            int u = __shfl_up_sync(0xffffffffu, w, o);
            if (lane >= o) w += u;
        }
        warp_sums[lane] = w;
    }
    __syncthreads();

    int excl = v - local + (warp > 0 ? warp_sums[warp - 1] : 0);

    int r = excl;
#pragma unroll
    for (int i = 0; i < PER; i++) {
        if (keep[i]) {
            g_src[b * SS + r] = t * PER + i;
            r++;
        }
    }
    if (t == 1023) g_counts[b] = excl + local;
}

// ---------------------------------------------------------------------------
// Kernel 2: gather + pad. One WARP per output row (b, j); 256-thread blocks
// handle 8 rows each. Each lane moves 4 float4s (lane + 32k) -> MLP=4 per
// thread. Streaming loads/stores (no reuse anywhere) keep L2 out of the way.
// ---------------------------------------------------------------------------
__global__ void __launch_bounds__(256)
gather_kernel(const float* __restrict__ x,
              float* __restrict__ out_padded,
              float* __restrict__ out_mask,
              int max_length, int total_rows) {
    const int warp_id = threadIdx.x >> 5;
    const int lane = threadIdx.x & 31;
    const int row = blockIdx.x * 8 + warp_id;
    if (row >= total_rows) return;

    const int b = row / max_length;
    const int j = row - b * max_length;
    const int count = g_counts[b];

    float4* dst = reinterpret_cast<float4*>(
        out_padded + (long long)row * DD);

    if (j < count) {
        const int s = g_src[b * SS + j];
        const float4* src = reinterpret_cast<const float4*>(
            x + ((long long)b * SS + s) * DD);
        float4 v0 = __ldcs(src + lane);
        float4 v1 = __ldcs(src + lane + 32);
        float4 v2 = __ldcs(src + lane + 64);
        float4 v3 = __ldcs(src + lane + 96);
        __stcs(dst + lane,      v0);
        __stcs(dst + lane + 32, v1);
        __stcs(dst + lane + 64, v2);
        __stcs(dst + lane + 96, v3);
    } else {
        const float4 z = make_float4(0.f, 0.f, 0.f, 0.f);
        __stcs(dst + lane,      z);
        __stcs(dst + lane + 32, z);
        __stcs(dst + lane + 64, z);
        __stcs(dst + lane + 96, z);
    }

    if (lane == 0) {
        out_mask[row] = (j < count) ? 1.0f : 0.0f;
    }
}

// ---------------------------------------------------------------------------
// Launch: out_size = B*ML*(D+1)  =>  ML = out_size / (B*(D+1))
// ---------------------------------------------------------------------------
extern "C" void kernel_launch(void* const* d_in, const int* in_sizes, int n_in,
                              void* d_out, int out_size) {
    const float* x       = (const float*)d_in[0];
    const float* probs   = (const float*)d_in[1];
    const float* uniform = (const float*)d_in[2];
    float* out = (float*)d_out;

    const int max_length = out_size / (BB * (DD + 1));
    float* out_mask = out + (long long)BB * max_length * DD;
    const int total_rows = BB * max_length;

    scan_kernel<<<BB, 1024>>>(probs, uniform);

    const int blocks = (total_rows + 7) / 8;
    gather_kernel<<<blocks, 256>>>(x, out, out_mask, max_length, total_rows);
}

// round 3
// speedup vs baseline: 1.3407x; 1.0879x over previous
#include <cuda_runtime.h>

// Problem constants (from reference: B, S, D = 16, 4096, 512)
#define BB 16
#define SS 4096
#define DD 512

// Scratch — per-batch compacted source indices + counts
__device__ int g_src[BB * SS];
__device__ int g_counts[BB];

// ---------------------------------------------------------------------------
// Kernel 1: per-batch stable compaction index build.
// One block per batch. 1024 threads x 4 elements (float4-vectorized loads).
// Block exclusive scan of keep flags gives each kept element its packed rank.
// ---------------------------------------------------------------------------
__global__ void __launch_bounds__(1024)
scan_kernel(const float4* __restrict__ probs4, const float4* __restrict__ uniform4) {
    const int b = blockIdx.x;
    const int t = threadIdx.x;
    const int idx4 = b * (SS / 4) + t;   // one float4 (=4 elements) per thread

    float4 p = probs4[idx4];
    float4 u = uniform4[idx4];

    int keep[4];
    keep[0] = (u.x >= p.x) ? 1 : 0;
    keep[1] = (u.y >= p.y) ? 1 : 0;
    keep[2] = (u.z >= p.z) ? 1 : 0;
    keep[3] = (u.w >= p.w) ? 1 : 0;
    int local = keep[0] + keep[1] + keep[2] + keep[3];

    const int lane = t & 31;
    const int warp = t >> 5;
    int v = local;
#pragma unroll
    for (int o = 1; o < 32; o <<= 1) {
        int uu = __shfl_up_sync(0xffffffffu, v, o);
        if (lane >= o) v += uu;
    }
    __shared__ int warp_sums[32];
    if (lane == 31) warp_sums[warp] = v;
    __syncthreads();
    if (warp == 0) {
        int w = warp_sums[lane];
#pragma unroll
        for (int o = 1; o < 32; o <<= 1) {
            int uu = __shfl_up_sync(0xffffffffu, w, o);
            if (lane >= o) w += uu;
        }
        warp_sums[lane] = w;
    }
    __syncthreads();

    int excl = v - local + (warp > 0 ? warp_sums[warp - 1] : 0);

    int r = excl;
#pragma unroll
    for (int i = 0; i < 4; i++) {
        if (keep[i]) {
            g_src[b * SS + r] = t * 4 + i;
            r++;
        }
    }
    if (t == 1023) g_counts[b] = excl + local;
}

// ---------------------------------------------------------------------------
// Kernel 2: gather + pad. Persistent grid; each warp handles 2 rows per
// iteration with all 8 LDG.128 front-batched (MLP=8/thread). Reads use
// default/cg policy (keep x resident in L2 across replays); stores are
// streaming (output never re-read; don't evict x).
// ---------------------------------------------------------------------------
__global__ void __launch_bounds__(256)
gather_kernel(const float* __restrict__ x,
              float* __restrict__ out_padded,
              float* __restrict__ out_mask,
              int max_length, int total_rows) {
    __shared__ int s_counts[BB];
    if (threadIdx.x < BB) s_counts[threadIdx.x] = g_counts[threadIdx.x];
    __syncthreads();

    const int lane = threadIdx.x & 31;
    const int gw   = blockIdx.x * 8 + (threadIdx.x >> 5);  // global warp id
    const int nw   = gridDim.x * 8;                        // total warps

    for (int r0 = gw; r0 < total_rows; r0 += 2 * nw) {
        const int r1 = r0 + nw;
        const bool has1 = (r1 < total_rows);

        const int b0 = r0 / max_length;
        const int j0 = r0 - b0 * max_length;
        const int b1 = has1 ? (r1 / max_length) : 0;
        const int j1 = has1 ? (r1 - b1 * max_length) : 0;

        const bool k0 = (j0 < s_counts[b0]);
        const bool k1 = has1 && (j1 < s_counts[b1]);

        // Index loads (both issued before data loads)
        int s0 = 0, s1 = 0;
        if (k0) s0 = __ldg(&g_src[b0 * SS + j0]);
        if (k1) s1 = __ldg(&g_src[b1 * SS + j1]);

        const float4 z = make_float4(0.f, 0.f, 0.f, 0.f);
        float4 v0 = z, v1 = z, v2 = z, v3 = z;
        float4 w0 = z, w1 = z, w2 = z, w3 = z;

        if (k0 && k1) {
            const float4* p0 = reinterpret_cast<const float4*>(
                x + ((long long)b0 * SS + s0) * DD);
            const float4* p1 = reinterpret_cast<const float4*>(
                x + ((long long)b1 * SS + s1) * DD);
            v0 = __ldcg(p0 + lane);
            v1 = __ldcg(p0 + lane + 32);
            v2 = __ldcg(p0 + lane + 64);
            v3 = __ldcg(p0 + lane + 96);
            w0 = __ldcg(p1 + lane);
            w1 = __ldcg(p1 + lane + 32);
            w2 = __ldcg(p1 + lane + 64);
            w3 = __ldcg(p1 + lane + 96);
        } else {
            if (k0) {
                const float4* p0 = reinterpret_cast<const float4*>(
                    x + ((long long)b0 * SS + s0) * DD);
                v0 = __ldcg(p0 + lane);
                v1 = __ldcg(p0 + lane + 32);
                v2 = __ldcg(p0 + lane + 64);
                v3 = __ldcg(p0 + lane + 96);
            }
            if (k1) {
                const float4* p1 = reinterpret_cast<const float4*>(
                    x + ((long long)b1 * SS + s1) * DD);
                w0 = __ldcg(p1 + lane);
                w1 = __ldcg(p1 + lane + 32);
                w2 = __ldcg(p1 + lane + 64);
                w3 = __ldcg(p1 + lane + 96);
            }
        }

        float4* d0 = reinterpret_cast<float4*>(out_padded + (long long)r0 * DD);
        __stcs(d0 + lane,      v0);
        __stcs(d0 + lane + 32, v1);
        __stcs(d0 + lane + 64, v2);
        __stcs(d0 + lane + 96, v3);
        if (has1) {
            float4* d1 = reinterpret_cast<float4*>(out_padded + (long long)r1 * DD);
            __stcs(d1 + lane,      w0);
            __stcs(d1 + lane + 32, w1);
            __stcs(d1 + lane + 64, w2);
            __stcs(d1 + lane + 96, w3);
        }

        if (lane == 0) {
            out_mask[r0] = k0 ? 1.0f : 0.0f;
            if (has1) out_mask[r1] = k1 ? 1.0f : 0.0f;
        }
    }
}

// ---------------------------------------------------------------------------
// Launch: out_size = B*ML*(D+1)  =>  ML = out_size / (B*(D+1))
// ---------------------------------------------------------------------------
extern "C" void kernel_launch(void* const* d_in, const int* in_sizes, int n_in,
                              void* d_out, int out_size) {
    const float* x       = (const float*)d_in[0];
    const float* probs   = (const float*)d_in[1];
    const float* uniform = (const float*)d_in[2];
    float* out = (float*)d_out;

    const int max_length = out_size / (BB * (DD + 1));
    float* out_mask = out + (long long)BB * max_length * DD;
    const int total_rows = BB * max_length;

    scan_kernel<<<BB, 1024>>>((const float4*)probs, (const float4*)uniform);

    const int blocks = 592;  // 148 SMs x 4 blocks (persistent single wave)
    gather_kernel<<<blocks, 256>>>(x, out, out_mask, max_length, total_rows);
}

// round 4
// speedup vs baseline: 1.3593x; 1.0139x over previous
#include <cuda_runtime.h>

// Problem constants (from reference: B, S, D = 16, 4096, 512)
#define BB 16
#define SS 4096
#define DD 512

// Scratch — per-batch compacted source indices + counts
__device__ int g_src[BB * SS];
__device__ int g_counts[BB];

// ---------------------------------------------------------------------------
// Kernel 1: per-batch stable compaction index build + mask output.
// One block per batch. 1024 threads x 4 elements (float4 loads). Block
// exclusive scan of keep flags gives each kept element its packed rank.
// Also writes this batch's mask row (out_mask[b*ML + j] = j < count).
// ---------------------------------------------------------------------------
__global__ void __launch_bounds__(1024)
scan_kernel(const float4* __restrict__ probs4, const float4* __restrict__ uniform4,
            float* __restrict__ out_mask, int max_length) {
    const int b = blockIdx.x;
    const int t = threadIdx.x;
    const int idx4 = b * (SS / 4) + t;

    float4 p = probs4[idx4];
    float4 u = uniform4[idx4];

    int keep[4];
    keep[0] = (u.x >= p.x) ? 1 : 0;
    keep[1] = (u.y >= p.y) ? 1 : 0;
    keep[2] = (u.z >= p.z) ? 1 : 0;
    keep[3] = (u.w >= p.w) ? 1 : 0;
    int local = keep[0] + keep[1] + keep[2] + keep[3];

    const int lane = t & 31;
    const int warp = t >> 5;
    int v = local;
#pragma unroll
    for (int o = 1; o < 32; o <<= 1) {
        int uu = __shfl_up_sync(0xffffffffu, v, o);
        if (lane >= o) v += uu;
    }
    __shared__ int warp_sums[32];
    __shared__ int s_total;
    if (lane == 31) warp_sums[warp] = v;
    __syncthreads();
    if (warp == 0) {
        int w = warp_sums[lane];
#pragma unroll
        for (int o = 1; o < 32; o <<= 1) {
            int uu = __shfl_up_sync(0xffffffffu, w, o);
            if (lane >= o) w += uu;
        }
        warp_sums[lane] = w;
        if (lane == 31) s_total = w;
    }
    __syncthreads();

    int excl = v - local + (warp > 0 ? warp_sums[warp - 1] : 0);

    int r = excl;
#pragma unroll
    for (int i = 0; i < 4; i++) {
        if (keep[i]) {
            g_src[b * SS + r] = t * 4 + i;
            r++;
        }
    }

    const int count = s_total;
    if (t == 0) g_counts[b] = count;

    // Write this batch's mask row: 1.0 for j < count else 0.0
    float* mrow = out_mask + (long long)b * max_length;
    for (int j = t; j < max_length; j += 1024) {
        mrow[j] = (j < count) ? 1.0f : 0.0f;
    }
}

// ---------------------------------------------------------------------------
// Kernel 2: gather + pad. Persistent grid, one row per warp per iteration,
// MLP=4 LDG.128 front-batched, lean registers for max occupancy.
// __ldcg reads (keep x resident in L2 across replays); __stcs stores
// (output never re-read; don't evict x).
// ---------------------------------------------------------------------------
__global__ void __launch_bounds__(256, 8)
gather_kernel(const float* __restrict__ x,
              float* __restrict__ out_padded,
              int max_length, int total_rows) {
    __shared__ int s_counts[BB];
    if (threadIdx.x < BB) s_counts[threadIdx.x] = g_counts[threadIdx.x];
    __syncthreads();

    const int lane = threadIdx.x & 31;
    const int gw   = blockIdx.x * 8 + (threadIdx.x >> 5);  // global warp id
    const int nw   = gridDim.x * 8;                        // total warps

    for (int row = gw; row < total_rows; row += nw) {
        const int b = row / max_length;
        const int j = row - b * max_length;

        float4* dst = reinterpret_cast<float4*>(out_padded + (long long)row * DD);

        if (j < s_counts[b]) {
            const int s = __ldg(&g_src[b * SS + j]);
            const float4* src = reinterpret_cast<const float4*>(
                x + ((long long)b * SS + s) * DD);
            float4 v0 = __ldcg(src + lane);
            float4 v1 = __ldcg(src + lane + 32);
            float4 v2 = __ldcg(src + lane + 64);
            float4 v3 = __ldcg(src + lane + 96);
            __stcs(dst + lane,      v0);
            __stcs(dst + lane + 32, v1);
            __stcs(dst + lane + 64, v2);
            __stcs(dst + lane + 96, v3);
        } else {
            const float4 z = make_float4(0.f, 0.f, 0.f, 0.f);
            __stcs(dst + lane,      z);
            __stcs(dst + lane + 32, z);
            __stcs(dst + lane + 64, z);
            __stcs(dst + lane + 96, z);
        }
    }
}

// ---------------------------------------------------------------------------
// Launch: out_size = B*ML*(D+1)  =>  ML = out_size / (B*(D+1))
// ---------------------------------------------------------------------------
extern "C" void kernel_launch(void* const* d_in, const int* in_sizes, int n_in,
                              void* d_out, int out_size) {
    const float* x       = (const float*)d_in[0];
    const float* probs   = (const float*)d_in[1];
    const float* uniform = (const float*)d_in[2];
    float* out = (float*)d_out;

    const int max_length = out_size / (BB * (DD + 1));
    float* out_mask = out + (long long)BB * max_length * DD;
    const int total_rows = BB * max_length;

    scan_kernel<<<BB, 1024>>>((const float4*)probs, (const float4*)uniform,
                              out_mask, max_length);

    const int blocks = 1184;  // 148 SMs x 8 blocks (persistent single wave)
    gather_kernel<<<blocks, 256>>>(x, out, max_length, total_rows);
}